// round 2
// baseline (speedup 1.0000x reference)
#include <cuda_runtime.h>
#include <cstdint>

#define WD 128
#define HT 128
#define NB 8
#define NC 16
#define HW (HT*WD)
#define CHW (NC*HW)
#define HO 127
#define WO 127
#define TR 8       // output rows per block
#define NSTRIP 16  // ceil(127/8)

typedef unsigned long long ull;

__device__ __forceinline__ ull pack2(float x, float y) {
    ull r;
    asm("mov.b64 %0, {%1, %2};" : "=l"(r) : "f"(x), "f"(y));
    return r;
}
__device__ __forceinline__ void unpack2(float& x, float& y, ull v) {
    asm("mov.b64 {%0, %1}, %2;" : "=f"(x), "=f"(y) : "l"(v));
}
__device__ __forceinline__ ull fma2(ull a, ull b, ull c) {
    ull d;
    asm("fma.rn.f32x2 %0, %1, %2, %3;" : "=l"(d) : "l"(a), "l"(b), "l"(c));
    return d;
}
// 16-byte shared load as two f32x2-ready 64-bit regs
__device__ __forceinline__ void lds_row(ull& lo, ull& hi, unsigned addr) {
    asm volatile("ld.shared.v2.u64 {%0, %1}, [%2];"
                 : "=l"(lo), "=l"(hi) : "r"(addr));
}

__global__ void __launch_bounds__(256) kan_fused_kernel(
    const float* __restrict__ x,
    const float* __restrict__ base_weight,
    const float* __restrict__ spline_weight,
    const float* __restrict__ spline_scaler,
    const float* __restrict__ grid,
    float* __restrict__ out)
{
    // Per-lane-replicated scaled spline weight table, padded.
    // Row p <-> basis j = p-3 (zero outside [0,8)); rows 14..17 are the
    // zero rows used for out-of-range inputs. Conflict-free LDS.128.
    __shared__ float4 tab[18 * 32];
    // Tap-contribution planes for this block's 9 eval rows.
    __shared__ float sa0[TR + 1][WD];
    __shared__ float sa1[TR + 1][WD];
    __shared__ float sa2[TR + 1][WD];
    __shared__ float sa3[TR + 1][WD];

    const int tid = threadIdx.x;

    for (int e = tid; e < 18 * 32; e += 256) {
        int p = e >> 5;
        int j = p - 3;
        float4 val = make_float4(0.f, 0.f, 0.f, 0.f);
        if (j >= 0 && j < 8) {
            val.x = spline_weight[0 * 8 + j] * spline_scaler[0];
            val.y = spline_weight[1 * 8 + j] * spline_scaler[1];
            val.z = spline_weight[2 * 8 + j] * spline_scaler[2];
            val.w = spline_weight[3 * 8 + j] * spline_scaler[3];
        }
        tab[e] = val;
    }
    __syncthreads();

    const float bw0 = __ldg(base_weight + 0);
    const float bw1 = __ldg(base_weight + 1);
    const float bw2 = __ldg(base_weight + 2);
    const float bw3 = __ldg(base_weight + 3);
    const float g0  = __ldg(grid + 0);
    const float invh = 1.0f / (__ldg(grid + 1) - g0);

    const ull bw01 = pack2(bw0, bw1);
    const ull bw23 = pack2(bw2, bw3);

    const int strip = blockIdx.x;
    const int b     = blockIdx.y;
    const int r0    = strip * TR;

    const unsigned tab_base =
        (unsigned)__cvta_generic_to_shared(tab) + (unsigned)((tid & 31) * 16);

    // ── Eval phase: 9 rows x 128 cols, channel-summed tap contributions ──
    for (int e = tid; e < (TR + 1) * WD; e += 256) {
        const int rl  = e >> 7;
        const int c   = e & (WD - 1);
        const int row = r0 + rl;
        if (row < HT) {
            const float* xp = x + b * CHW + row * WD + c;
            ull acc01 = 0ull, acc23 = 0ull;

#pragma unroll
            for (int ch = 0; ch < NC; ch++) {
                const float v = __ldg(xp + ch * HW);

                const float p  = (v - g0) * invh;
                const float fc = floorf(p);
                const float u  = p - fc;
                const int cell = (int)fc;
                const int cb   = ((unsigned)cell <= 10u) ? cell : 14;

                // SiLU base path
                const float s = __fdividef(v, 1.f + __expf(-v));
                const ull s2 = pack2(s, s);
                acc01 = fma2(s2, bw01, acc01);
                acc23 = fma2(s2, bw23, acc23);

                // Uniform cubic B-spline weights (already /6), scalar Horner
                const float w0 = fmaf(fmaf(fmaf(-(1.f/6.f), u, 0.5f), u, -0.5f), u, 1.f/6.f);
                const float w1 = fmaf(fmaf(fmaf(0.5f, u, -1.f), u, 0.f), u, 2.f/3.f);
                const float w2 = fmaf(fmaf(fmaf(-0.5f, u, 0.5f), u, 0.5f), u, 1.f/6.f);
                const float w3 = u * u * u * (1.f/6.f);

                const unsigned a = tab_base + (unsigned)(cb * 512);
                ull r0lo, r0hi, r1lo, r1hi, r2lo, r2hi, r3lo, r3hi;
                lds_row(r0lo, r0hi, a);
                lds_row(r1lo, r1hi, a + 512);
                lds_row(r2lo, r2hi, a + 1024);
                lds_row(r3lo, r3hi, a + 1536);

                const ull w0p = pack2(w0, w0);
                const ull w1p = pack2(w1, w1);
                const ull w2p = pack2(w2, w2);
                const ull w3p = pack2(w3, w3);

                acc01 = fma2(w0p, r0lo, acc01); acc23 = fma2(w0p, r0hi, acc23);
                acc01 = fma2(w1p, r1lo, acc01); acc23 = fma2(w1p, r1hi, acc23);
                acc01 = fma2(w2p, r2lo, acc01); acc23 = fma2(w2p, r2hi, acc23);
                acc01 = fma2(w3p, r3lo, acc01); acc23 = fma2(w3p, r3hi, acc23);
            }

            float a0, a1, a2, a3;
            unpack2(a0, a1, acc01);
            unpack2(a2, a3, acc23);
            sa0[rl][c] = a0;
            sa1[rl][c] = a1;
            sa2[rl][c] = a2;
            sa3[rl][c] = a3;
        }
    }

    __syncthreads();

    // ── Combine phase: out(r,c) = a0(r,c)+a1(r,c+1)+a2(r+1,c)+a3(r+1,c+1) ──
#pragma unroll
    for (int o = tid; o < TR * WD; o += 256) {
        const int rl = o >> 7;
        const int c  = o & (WD - 1);
        const int r  = r0 + rl;
        if (r < HO && c < WO) {
            const float val = sa0[rl][c] + sa1[rl][c + 1] +
                              sa2[rl + 1][c] + sa3[rl + 1][c + 1];
            out[(b * HO + r) * WO + c] = val;
        }
    }
}

extern "C" void kernel_launch(void* const* d_in, const int* in_sizes, int n_in,
                              void* d_out, int out_size)
{
    const float* x  = (const float*)d_in[0];
    const float* bw = (const float*)d_in[1];
    const float* sw = (const float*)d_in[2];
    const float* ss = (const float*)d_in[3];
    const float* gr = (const float*)d_in[4];
    float* out = (float*)d_out;

    (void)in_sizes; (void)n_in; (void)out_size;

    dim3 gs(NSTRIP, NB, 1);
    kan_fused_kernel<<<gs, 256>>>(x, bw, sw, ss, gr, out);
}